// round 12
// baseline (speedup 1.0000x reference)
#include <cuda_runtime.h>
#include <cstdint>
#include <math.h>

#define NN 50000
#define EE 800000
#define DD 128
#define KK 64
#define BN_EPS_F 1e-5f
#define SCAN_NB 49
#define NT64 ((NN + 63) / 64)    // 782

#define BAR_SYNC(id, cnt)   asm volatile("bar.sync %0, %1;"   :: "r"(id), "r"(cnt) : "memory")
#define BAR_ARRIVE(id, cnt) asm volatile("bar.arrive %0, %1;" :: "r"(id), "r"(cnt) : "memory")

// ---------------- scratch (static device memory) ----------------
__device__ float  g_agg_unused[1];
__device__ float  g_h[NN * DD];
__device__ float  g_h2[NN * DD];
__device__ double g_stats[4 * DD];
__device__ float  g_scale[DD];
__device__ float  g_shift[DD];
// CSR
__device__ int g_deg[NN], g_off[NN + 1], g_cursor[NN], g_csr[EE], g_bsum[SCAN_NB];

// ---------------- zero degree + stats ----------------
__global__ void k_zero() {
    int i = blockIdx.x * blockDim.x + threadIdx.x;
    if (i < NN) g_deg[i] = 0;
    if (i < 512) g_stats[i] = 0.0;
}

// ---------------- in-degree histogram ----------------
__global__ void k_hist(const int* __restrict__ ei) {
    int e = blockIdx.x * blockDim.x + threadIdx.x;
    if (e >= EE) return;
    int d = __ldg(ei + EE + e);
    if ((unsigned)d < NN) atomicAdd(&g_deg[d], 1);
}

// ---------------- scan phase 1 ----------------
__global__ void __launch_bounds__(1024) k_scan1() {
    __shared__ int swarp[32];
    int b = blockIdx.x, tid = threadIdx.x;
    int lane = tid & 31, w = tid >> 5;
    int i = b * 1024 + tid;
    int v = (i < NN) ? g_deg[i] : 0;
    int xv = v;
    #pragma unroll
    for (int o = 1; o < 32; o <<= 1) {
        int y = __shfl_up_sync(0xffffffffu, xv, o);
        if (lane >= o) xv += y;
    }
    if (lane == 31) swarp[w] = xv;
    __syncthreads();
    if (w == 0) {
        int y = swarp[lane];
        #pragma unroll
        for (int o = 1; o < 32; o <<= 1) {
            int z = __shfl_up_sync(0xffffffffu, y, o);
            if (lane >= o) y += z;
        }
        swarp[lane] = y;
    }
    __syncthreads();
    int excl = xv - v + (w > 0 ? swarp[w - 1] : 0);
    if (i < NN) g_off[i] = excl;
    if (tid == 1023) g_bsum[b] = excl + v;
}

// ---------------- scan phase 2 ----------------
__global__ void __launch_bounds__(1024) k_scan2() {
    __shared__ int partial[2];
    int b = blockIdx.x, tid = threadIdx.x;
    int v = 0;
    if (tid < 64) {
        if (tid < SCAN_NB && tid < b) v = g_bsum[tid];
        #pragma unroll
        for (int o = 16; o > 0; o >>= 1) v += __shfl_down_sync(0xffffffffu, v, o);
        if ((tid & 31) == 0) partial[tid >> 5] = v;
    }
    __syncthreads();
    int base = partial[0] + partial[1];
    int i = b * 1024 + tid;
    if (i < NN) {
        int o = g_off[i] + base;
        g_off[i] = o;
        g_cursor[i] = o;
    }
    if (b == SCAN_NB - 1 && tid == 0) g_off[NN] = base + g_bsum[b];
}

// ---------------- permute ----------------
__global__ void k_permute(const int* __restrict__ ei) {
    int e = blockIdx.x * blockDim.x + threadIdx.x;
    if (e >= EE) return;
    int s = __ldg(ei + e);
    int d = __ldg(ei + EE + e);
    if ((unsigned)s >= NN || (unsigned)d >= NN) return;
    int pos = atomicAdd(&g_cursor[d], 1);
    g_csr[pos] = s;
}

// ---------------- fused gather + 2-GEMM MLP (warp-specialized, double-buffered) ----------------
// 384 threads: warps 0-7 consumers (GEMM), warps 8-11 producers (CSR gather).
// smem floats: sWa 16384 | sWb 16384 | buf0 8192 | buf1 8192 | sT 8192 | sS 256 = 57600 (230400 B)
// barriers: 4/5 = full(buf0/1), 6/7 = empty(buf0/1), 3 = consumer-internal.
__global__ void __launch_bounds__(384, 1) k_mlp_fused(
    const float* __restrict__ feat, const float* __restrict__ epsp,
    const float* __restrict__ Wa, const float* __restrict__ ba,
    const float* __restrict__ Wb, const float* __restrict__ bb,
    float* __restrict__ hout, int layer)
{
    extern __shared__ float sm[];
    float* sWa  = sm;
    float* sWb  = sm + 16384;
    float* sT   = sm + 49152;
    float* sS   = sm + 57344;

    int tid = threadIdx.x;
    for (int i = tid; i < 4096; i += 384) {
        ((float4*)sWa)[i] = ((const float4*)Wa)[i];
        ((float4*)sWb)[i] = ((const float4*)Wb)[i];
    }
    if (tid < 256) sS[tid] = 0.0f;
    __syncthreads();

    if (tid < 256) {
        // ================= CONSUMERS =================
        int tx = tid & 31;
        int ty = tid >> 5;
        float4 ba4 = *(const float4*)(ba + tx * 4);
        float4 bb4 = *(const float4*)(bb + tx * 4);

        int l = 0;
        for (int t = blockIdx.x; t < NT64; t += 148, l++) {
            int row0 = t * 64;
            int rows = NN - row0; if (rows > 64) rows = 64;
            BAR_SYNC(4 + (l & 1), 384);           // wait buffer full
            const float* buf = sm + 32768 + (l & 1) * 8192;

            // GEMM1: T = relu(buf @ Wa + ba)
            float acc[8][4];
            #pragma unroll
            for (int r = 0; r < 8; r++) { acc[r][0] = ba4.x; acc[r][1] = ba4.y; acc[r][2] = ba4.z; acc[r][3] = ba4.w; }
            #pragma unroll 8
            for (int k = 0; k < DD; k++) {
                float4 w = ((const float4*)(sWa + k * DD))[tx];
                #pragma unroll
                for (int r = 0; r < 8; r++) {
                    float a = buf[(ty * 8 + r) * DD + k];
                    acc[r][0] = fmaf(a, w.x, acc[r][0]);
                    acc[r][1] = fmaf(a, w.y, acc[r][1]);
                    acc[r][2] = fmaf(a, w.z, acc[r][2]);
                    acc[r][3] = fmaf(a, w.w, acc[r][3]);
                }
            }
            BAR_ARRIVE(6 + (l & 1), 384);         // buffer consumed -> producers may refill

            #pragma unroll
            for (int r = 0; r < 8; r++) {
                float4 v = make_float4(fmaxf(acc[r][0], 0.f), fmaxf(acc[r][1], 0.f),
                                       fmaxf(acc[r][2], 0.f), fmaxf(acc[r][3], 0.f));
                ((float4*)(sT + (ty * 8 + r) * DD))[tx] = v;
            }
            BAR_SYNC(3, 256);                     // sT visible to all consumers

            // GEMM2: h = T @ Wb + bb
            #pragma unroll
            for (int r = 0; r < 8; r++) { acc[r][0] = bb4.x; acc[r][1] = bb4.y; acc[r][2] = bb4.z; acc[r][3] = bb4.w; }
            #pragma unroll 8
            for (int k = 0; k < DD; k++) {
                float4 w = ((const float4*)(sWb + k * DD))[tx];
                #pragma unroll
                for (int r = 0; r < 8; r++) {
                    float a = sT[(ty * 8 + r) * DD + k];
                    acc[r][0] = fmaf(a, w.x, acc[r][0]);
                    acc[r][1] = fmaf(a, w.y, acc[r][1]);
                    acc[r][2] = fmaf(a, w.z, acc[r][2]);
                    acc[r][3] = fmaf(a, w.w, acc[r][3]);
                }
            }
            BAR_SYNC(3, 256);                     // GEMM2 reads done before next sT overwrite

            // epilogue: store h + column stats
            float s0 = 0.f, s1 = 0.f, s2 = 0.f, s3 = 0.f;
            float q0 = 0.f, q1 = 0.f, q2 = 0.f, q3 = 0.f;
            #pragma unroll
            for (int r = 0; r < 8; r++) {
                int rr = ty * 8 + r;
                if (rr < rows) {
                    float4 v = make_float4(acc[r][0], acc[r][1], acc[r][2], acc[r][3]);
                    ((float4*)(hout + (size_t)(row0 + rr) * DD))[tx] = v;
                    s0 += v.x; q0 += v.x * v.x;
                    s1 += v.y; q1 += v.y * v.y;
                    s2 += v.z; q2 += v.z * v.z;
                    s3 += v.w; q3 += v.w * v.w;
                }
            }
            int c = tx * 4;
            atomicAdd(&sS[c + 0], s0); atomicAdd(&sS[128 + c + 0], q0);
            atomicAdd(&sS[c + 1], s1); atomicAdd(&sS[128 + c + 1], q1);
            atomicAdd(&sS[c + 2], s2); atomicAdd(&sS[128 + c + 2], q2);
            atomicAdd(&sS[c + 3], s3); atomicAdd(&sS[128 + c + 3], q3);
        }
        BAR_SYNC(3, 256);
        atomicAdd(&g_stats[layer * 256 + tid], (double)sS[tid]);
    } else {
        // ================= PRODUCERS =================
        int ptid = tid - 256;
        int pw = ptid >> 5, lane = ptid & 31;
        float e = 1.0f + *epsp;
        float4 sc = make_float4(0, 0, 0, 0), sh = make_float4(0, 0, 0, 0);
        if (layer) { sc = ((const float4*)g_scale)[lane]; sh = ((const float4*)g_shift)[lane]; }

        #define BNZ(v) do { \
            (v).x = fmaxf(fmaf((v).x, sc.x, sh.x), 0.f); \
            (v).y = fmaxf(fmaf((v).y, sc.y, sh.y), 0.f); \
            (v).z = fmaxf(fmaf((v).z, sc.z, sh.z), 0.f); \
            (v).w = fmaxf(fmaf((v).w, sc.w, sh.w), 0.f); } while (0)

        int l = 0;
        for (int t = blockIdx.x; t < NT64; t += 148, l++) {
            if (l >= 2) BAR_SYNC(6 + (l & 1), 384);   // wait buffer empty
            float* buf = sm + 32768 + (l & 1) * 8192;

            for (int r = pw; r < 64; r += 4) {
                int node = t * 64 + r;
                float4 acc = make_float4(0.f, 0.f, 0.f, 0.f);
                if (node < NN) {
                    acc = __ldg((const float4*)(feat + (size_t)node * DD) + lane);
                    if (layer) BNZ(acc);
                    acc.x *= e; acc.y *= e; acc.z *= e; acc.w *= e;
                    int beg = __ldg(&g_off[node]);
                    int end = __ldg(&g_off[node + 1]);
                    int j = beg;
                    for (; j + 4 <= end; j += 4) {
                        int s0i = __ldg(&g_csr[j]);
                        int s1i = __ldg(&g_csr[j + 1]);
                        int s2i = __ldg(&g_csr[j + 2]);
                        int s3i = __ldg(&g_csr[j + 3]);
                        float4 v0 = __ldg((const float4*)(feat + (size_t)s0i * DD) + lane);
                        float4 v1 = __ldg((const float4*)(feat + (size_t)s1i * DD) + lane);
                        float4 v2 = __ldg((const float4*)(feat + (size_t)s2i * DD) + lane);
                        float4 v3 = __ldg((const float4*)(feat + (size_t)s3i * DD) + lane);
                        if (layer) { BNZ(v0); BNZ(v1); BNZ(v2); BNZ(v3); }
                        acc.x += (v0.x + v1.x) + (v2.x + v3.x);
                        acc.y += (v0.y + v1.y) + (v2.y + v3.y);
                        acc.z += (v0.z + v1.z) + (v2.z + v3.z);
                        acc.w += (v0.w + v1.w) + (v2.w + v3.w);
                    }
                    for (; j < end; j++) {
                        int si = __ldg(&g_csr[j]);
                        float4 v = __ldg((const float4*)(feat + (size_t)si * DD) + lane);
                        if (layer) BNZ(v);
                        acc.x += v.x; acc.y += v.y; acc.z += v.z; acc.w += v.w;
                    }
                }
                *(float4*)(buf + r * DD + lane * 4) = acc;
            }
            BAR_ARRIVE(4 + (l & 1), 384);             // buffer full
        }
        #undef BNZ
    }
}

// ---------------- BN finalize ----------------
__global__ void k_bnstats(const float* __restrict__ gamma, const float* __restrict__ beta, int layer) {
    int c = threadIdx.x;
    double s = g_stats[layer * 256 + c];
    double q = g_stats[layer * 256 + 128 + c];
    float m = (float)(s / (double)NN);
    float v = (float)(q / (double)NN) - m * m;
    float sc = gamma[c] * rsqrtf(v + BN_EPS_F);
    g_scale[c] = sc;
    g_shift[c] = beta[c] - m * sc;
}

// ---------------- final: persistent; z2 = relu(bn(h2)); logits; softmax ----------------
#define FIN_TILES ((NN + 15) / 16)
__global__ void __launch_bounds__(128) k_final(
    const float* __restrict__ Wout, const float* __restrict__ log_tau,
    float* __restrict__ out)
{
    __shared__ float sW[DD * KK];
    __shared__ float sZ[16 * DD];
    int tid = threadIdx.x;
    for (int i = tid; i < DD * KK / 4; i += 128)
        ((float4*)sW)[i] = ((const float4*)Wout)[i];

    int warp = tid >> 5, lane = tid & 31;
    float inv_tau = expf(-*log_tau);

    for (int t = blockIdx.x; t < FIN_TILES; t += gridDim.x) {
        int row0 = t * 16;
        __syncthreads();
        for (int i = tid; i < 16 * DD / 4; i += 128) {
            int r = i >> 5;
            int c4 = i & 31;
            float4 v = make_float4(0.f, 0.f, 0.f, 0.f);
            int row = row0 + r;
            if (row < NN) {
                float4 hv = ((const float4*)(g_h2 + (size_t)row * DD))[c4];
                float4 sc = ((const float4*)g_scale)[c4];
                float4 sh = ((const float4*)g_shift)[c4];
                v.x = fmaxf(fmaf(hv.x, sc.x, sh.x), 0.f);
                v.y = fmaxf(fmaf(hv.y, sc.y, sh.y), 0.f);
                v.z = fmaxf(fmaf(hv.z, sc.z, sh.z), 0.f);
                v.w = fmaxf(fmaf(hv.w, sc.w, sh.w), 0.f);
            }
            ((float4*)sZ)[i] = v;
        }
        __syncthreads();

        float acc[4][2];
        #pragma unroll
        for (int r = 0; r < 4; r++) { acc[r][0] = 0.f; acc[r][1] = 0.f; }
        #pragma unroll 4
        for (int k = 0; k < DD; k++) {
            float w0 = sW[k * KK + lane];
            float w1 = sW[k * KK + 32 + lane];
            #pragma unroll
            for (int r = 0; r < 4; r++) {
                float z = sZ[(warp * 4 + r) * DD + k];
                acc[r][0] = fmaf(z, w0, acc[r][0]);
                acc[r][1] = fmaf(z, w1, acc[r][1]);
            }
        }

        #pragma unroll
        for (int r = 0; r < 4; r++) {
            int row = row0 + warp * 4 + r;
            if (row >= NN) continue;
            float l0 = acc[r][0], l1 = acc[r][1];
            out[(size_t)NN * KK + (size_t)row * KK + lane]      = l0;
            out[(size_t)NN * KK + (size_t)row * KK + 32 + lane] = l1;
            float a0 = l0 * inv_tau, a1 = l1 * inv_tau;
            float m = fmaxf(a0, a1);
            #pragma unroll
            for (int o = 16; o > 0; o >>= 1) m = fmaxf(m, __shfl_xor_sync(0xffffffffu, m, o));
            float e0 = expf(a0 - m), e1 = expf(a1 - m);
            float s = e0 + e1;
            #pragma unroll
            for (int o = 16; o > 0; o >>= 1) s += __shfl_xor_sync(0xffffffffu, s, o);
            float inv = 1.0f / s;
            out[(size_t)row * KK + lane]      = e0 * inv;
            out[(size_t)row * KK + 32 + lane] = e1 * inv;
        }
    }
}

// ---------------- launch ----------------
extern "C" void kernel_launch(void* const* d_in, const int* in_sizes, int n_in,
                              void* d_out, int out_size) {
    const float* x      = (const float*)d_in[0];
    const int*   ei     = (const int*)d_in[1];
    const float* W1a    = (const float*)d_in[2];
    const float* b1a    = (const float*)d_in[3];
    const float* W1b    = (const float*)d_in[4];
    const float* b1b    = (const float*)d_in[5];
    const float* eps1   = (const float*)d_in[6];
    const float* gamma1 = (const float*)d_in[7];
    const float* beta1  = (const float*)d_in[8];
    const float* W2a    = (const float*)d_in[9];
    const float* b2a    = (const float*)d_in[10];
    const float* W2b    = (const float*)d_in[11];
    const float* b2b    = (const float*)d_in[12];
    const float* eps2   = (const float*)d_in[13];
    const float* gamma2 = (const float*)d_in[14];
    const float* beta2  = (const float*)d_in[15];
    const float* Wout   = (const float*)d_in[16];
    const float* ltau   = (const float*)d_in[17];
    float* out = (float*)d_out;

    float* hptr = nullptr, *h2ptr = nullptr;
    cudaGetSymbolAddress((void**)&hptr, g_h);
    cudaGetSymbolAddress((void**)&h2ptr, g_h2);

    const int FUSED_SMEM = 57600 * 4;   // 230400 B
    cudaFuncSetAttribute(k_mlp_fused, cudaFuncAttributeMaxDynamicSharedMemorySize, FUSED_SMEM);

    int n_blocks = (NN + 255) / 256;
    int e_blocks = (EE + 255) / 256;

    // CSR build
    k_zero<<<n_blocks, 256>>>();
    k_hist<<<e_blocks, 256>>>(ei);
    k_scan1<<<SCAN_NB, 1024>>>();
    k_scan2<<<SCAN_NB, 1024>>>();
    k_permute<<<e_blocks, 256>>>(ei);

    // layer 1: gather(x) fused with MLP -> g_h
    k_mlp_fused<<<148, 384, FUSED_SMEM>>>(x, eps1, W1a, b1a, W1b, b1b, hptr, 0);
    k_bnstats<<<1, 128>>>(gamma1, beta1, 0);

    // layer 2: gather(bn-relu(g_h)) fused with MLP -> g_h2
    k_mlp_fused<<<148, 384, FUSED_SMEM>>>(hptr, eps2, W2a, b2a, W2b, b2b, h2ptr, 1);
    k_bnstats<<<1, 128>>>(gamma2, beta2, 1);

    k_final<<<592, 128>>>(Wout, ltau, out);
}

// round 13
// speedup vs baseline: 1.7232x; 1.7232x over previous
#include <cuda_runtime.h>
#include <cstdint>
#include <math.h>

#define NN 50000
#define EE 800000
#define DD 128
#define KK 64
#define BN_EPS_F 1e-5f
#define SCAN_NB 49

// ---------------- scratch (static device memory) ----------------
__device__ float  g_agg[NN * DD];
__device__ float  g_h[NN * DD];
__device__ double g_stats[4 * DD];
// CSR
__device__ int g_deg[NN], g_off[NN + 1], g_cursor[NN], g_csr[EE], g_bsum[SCAN_NB];

// ---------------- zero degree + stats ----------------
__global__ void k_zero() {
    int i = blockIdx.x * blockDim.x + threadIdx.x;
    if (i < NN) g_deg[i] = 0;
    if (i < 512) g_stats[i] = 0.0;
}

// ---------------- in-degree histogram ----------------
__global__ void k_hist(const int* __restrict__ ei) {
    int e = blockIdx.x * blockDim.x + threadIdx.x;
    if (e >= EE) return;
    int d = __ldg(ei + EE + e);
    if ((unsigned)d < NN) atomicAdd(&g_deg[d], 1);
}

// ---------------- scan phase 1 ----------------
__global__ void __launch_bounds__(1024) k_scan1() {
    __shared__ int swarp[32];
    int b = blockIdx.x, tid = threadIdx.x;
    int lane = tid & 31, w = tid >> 5;
    int i = b * 1024 + tid;
    int v = (i < NN) ? g_deg[i] : 0;
    int xv = v;
    #pragma unroll
    for (int o = 1; o < 32; o <<= 1) {
        int y = __shfl_up_sync(0xffffffffu, xv, o);
        if (lane >= o) xv += y;
    }
    if (lane == 31) swarp[w] = xv;
    __syncthreads();
    if (w == 0) {
        int y = swarp[lane];
        #pragma unroll
        for (int o = 1; o < 32; o <<= 1) {
            int z = __shfl_up_sync(0xffffffffu, y, o);
            if (lane >= o) y += z;
        }
        swarp[lane] = y;
    }
    __syncthreads();
    int excl = xv - v + (w > 0 ? swarp[w - 1] : 0);
    if (i < NN) g_off[i] = excl;
    if (tid == 1023) g_bsum[b] = excl + v;
}

// ---------------- scan phase 2 ----------------
__global__ void __launch_bounds__(1024) k_scan2() {
    __shared__ int partial[2];
    int b = blockIdx.x, tid = threadIdx.x;
    int v = 0;
    if (tid < 64) {
        if (tid < SCAN_NB && tid < b) v = g_bsum[tid];
        #pragma unroll
        for (int o = 16; o > 0; o >>= 1) v += __shfl_down_sync(0xffffffffu, v, o);
        if ((tid & 31) == 0) partial[tid >> 5] = v;
    }
    __syncthreads();
    int base = partial[0] + partial[1];
    int i = b * 1024 + tid;
    if (i < NN) {
        int o = g_off[i] + base;
        g_off[i] = o;
        g_cursor[i] = o;
    }
    if (b == SCAN_NB - 1 && tid == 0) g_off[NN] = base + g_bsum[b];
}

// ---------------- permute ----------------
__global__ void k_permute(const int* __restrict__ ei) {
    int e = blockIdx.x * blockDim.x + threadIdx.x;
    if (e >= EE) return;
    int s = __ldg(ei + e);
    int d = __ldg(ei + EE + e);
    if ((unsigned)s >= NN || (unsigned)d >= NN) return;
    int pos = atomicAdd(&g_cursor[d], 1);
    g_csr[pos] = s;
}

// ---------------- gather (layer 1): agg[n] = (1+eps)*x[n] + sum x[j] ----------------
__global__ void k_gather(const float* __restrict__ feat, const float* __restrict__ epsp) {
    int gw = (blockIdx.x * blockDim.x + threadIdx.x) >> 5;
    int lane = threadIdx.x & 31;
    if (gw >= NN) return;
    float e = 1.0f + *epsp;
    float4 acc = __ldg((const float4*)(feat + (size_t)gw * DD) + lane);
    acc.x *= e; acc.y *= e; acc.z *= e; acc.w *= e;
    int beg = __ldg(&g_off[gw]);
    int end = __ldg(&g_off[gw + 1]);
    int j = beg;
    for (; j + 4 <= end; j += 4) {
        int s0 = __ldg(&g_csr[j]);
        int s1 = __ldg(&g_csr[j + 1]);
        int s2 = __ldg(&g_csr[j + 2]);
        int s3 = __ldg(&g_csr[j + 3]);
        float4 v0 = __ldg((const float4*)(feat + (size_t)s0 * DD) + lane);
        float4 v1 = __ldg((const float4*)(feat + (size_t)s1 * DD) + lane);
        float4 v2 = __ldg((const float4*)(feat + (size_t)s2 * DD) + lane);
        float4 v3 = __ldg((const float4*)(feat + (size_t)s3 * DD) + lane);
        acc.x += (v0.x + v1.x) + (v2.x + v3.x);
        acc.y += (v0.y + v1.y) + (v2.y + v3.y);
        acc.z += (v0.z + v1.z) + (v2.z + v3.z);
        acc.w += (v0.w + v1.w) + (v2.w + v3.w);
    }
    for (; j < end; j++) {
        int s = __ldg(&g_csr[j]);
        float4 v = __ldg((const float4*)(feat + (size_t)s * DD) + lane);
        acc.x += v.x; acc.y += v.y; acc.z += v.z; acc.w += v.w;
    }
    ((float4*)(g_agg + (size_t)gw * DD))[lane] = acc;
}

// ---------------- gather layer 2: fused BN(from g_stats)+relu, reads g_h ----------------
__global__ void k_gather_bn(const float* __restrict__ epsp,
                            const float* __restrict__ gamma, const float* __restrict__ beta) {
    __shared__ float sSc[DD], sSh[DD];
    if (threadIdx.x < DD) {
        int c = threadIdx.x;
        double s = g_stats[c];
        double q = g_stats[DD + c];
        float m = (float)(s / (double)NN);
        float v = (float)(q / (double)NN) - m * m;
        float sc = gamma[c] * rsqrtf(v + BN_EPS_F);
        sSc[c] = sc;
        sSh[c] = beta[c] - m * sc;
    }
    __syncthreads();

    int gw = (blockIdx.x * blockDim.x + threadIdx.x) >> 5;
    int lane = threadIdx.x & 31;
    if (gw >= NN) return;
    float e = 1.0f + *epsp;
    float4 sc = ((const float4*)sSc)[lane];
    float4 sh = ((const float4*)sSh)[lane];

    #define BNZ(v) do { \
        (v).x = fmaxf(fmaf((v).x, sc.x, sh.x), 0.f); \
        (v).y = fmaxf(fmaf((v).y, sc.y, sh.y), 0.f); \
        (v).z = fmaxf(fmaf((v).z, sc.z, sh.z), 0.f); \
        (v).w = fmaxf(fmaf((v).w, sc.w, sh.w), 0.f); } while (0)

    float4 acc = __ldg((const float4*)(g_h + (size_t)gw * DD) + lane);
    BNZ(acc);
    acc.x *= e; acc.y *= e; acc.z *= e; acc.w *= e;
    int beg = __ldg(&g_off[gw]);
    int end = __ldg(&g_off[gw + 1]);
    int j = beg;
    for (; j + 4 <= end; j += 4) {
        int s0 = __ldg(&g_csr[j]);
        int s1 = __ldg(&g_csr[j + 1]);
        int s2 = __ldg(&g_csr[j + 2]);
        int s3 = __ldg(&g_csr[j + 3]);
        float4 v0 = __ldg((const float4*)(g_h + (size_t)s0 * DD) + lane);
        float4 v1 = __ldg((const float4*)(g_h + (size_t)s1 * DD) + lane);
        float4 v2 = __ldg((const float4*)(g_h + (size_t)s2 * DD) + lane);
        float4 v3 = __ldg((const float4*)(g_h + (size_t)s3 * DD) + lane);
        BNZ(v0); BNZ(v1); BNZ(v2); BNZ(v3);
        acc.x += (v0.x + v1.x) + (v2.x + v3.x);
        acc.y += (v0.y + v1.y) + (v2.y + v3.y);
        acc.z += (v0.z + v1.z) + (v2.z + v3.z);
        acc.w += (v0.w + v1.w) + (v2.w + v3.w);
    }
    for (; j < end; j++) {
        int s = __ldg(&g_csr[j]);
        float4 v = __ldg((const float4*)(g_h + (size_t)s * DD) + lane);
        BNZ(v);
        acc.x += v.x; acc.y += v.y; acc.z += v.z; acc.w += v.w;
    }
    #undef BNZ
    ((float4*)(g_agg + (size_t)gw * DD))[lane] = acc;
}

// ---------------- fused 2-GEMM MLP (fp32 FFMA) + BN stats ----------------
__global__ void __launch_bounds__(256, 1) k_mlp(
    const float* __restrict__ Wa, const float* __restrict__ ba,
    const float* __restrict__ Wb, const float* __restrict__ bb, int layer)
{
    extern __shared__ float sm[];
    float* sWa = sm;
    float* sWb = sm + 16384;
    float* sA  = sm + 32768;
    float* sT  = sm + 40960;
    float* sS  = sm + 49152;

    int tid = threadIdx.x;
    for (int i = tid; i < 4096; i += 256) {
        ((float4*)sWa)[i] = ((const float4*)Wa)[i];
        ((float4*)sWb)[i] = ((const float4*)Wb)[i];
    }
    sS[tid] = 0.0f;

    int tx = tid & 31;
    int ty = tid >> 5;
    float4 ba4 = *(const float4*)(ba + tx * 4);
    float4 bb4 = *(const float4*)(bb + tx * 4);
    __syncthreads();

    const int ntiles = (NN + 63) / 64;
    for (int t = blockIdx.x; t < ntiles; t += gridDim.x) {
        int row0 = t * 64;
        int rows = NN - row0; if (rows > 64) rows = 64;

        for (int i = tid; i < 2048; i += 256) {
            int r = i >> 5;
            float4 v = make_float4(0.f, 0.f, 0.f, 0.f);
            if (r < rows) v = ((const float4*)(g_agg + (size_t)(row0 + r) * DD))[i & 31];
            ((float4*)sA)[i] = v;
        }
        __syncthreads();

        float acc[8][4];
        #pragma unroll
        for (int r = 0; r < 8; r++) { acc[r][0] = ba4.x; acc[r][1] = ba4.y; acc[r][2] = ba4.z; acc[r][3] = ba4.w; }
        #pragma unroll 8
        for (int k = 0; k < DD; k++) {
            float4 w = ((const float4*)(sWa + k * DD))[tx];
            #pragma unroll
            for (int r = 0; r < 8; r++) {
                float a = sA[(ty * 8 + r) * DD + k];
                acc[r][0] = fmaf(a, w.x, acc[r][0]);
                acc[r][1] = fmaf(a, w.y, acc[r][1]);
                acc[r][2] = fmaf(a, w.z, acc[r][2]);
                acc[r][3] = fmaf(a, w.w, acc[r][3]);
            }
        }
        #pragma unroll
        for (int r = 0; r < 8; r++) {
            float4 v = make_float4(fmaxf(acc[r][0], 0.f), fmaxf(acc[r][1], 0.f),
                                   fmaxf(acc[r][2], 0.f), fmaxf(acc[r][3], 0.f));
            ((float4*)(sT + (ty * 8 + r) * DD))[tx] = v;
        }
        __syncthreads();

        #pragma unroll
        for (int r = 0; r < 8; r++) { acc[r][0] = bb4.x; acc[r][1] = bb4.y; acc[r][2] = bb4.z; acc[r][3] = bb4.w; }
        #pragma unroll 8
        for (int k = 0; k < DD; k++) {
            float4 w = ((const float4*)(sWb + k * DD))[tx];
            #pragma unroll
            for (int r = 0; r < 8; r++) {
                float a = sT[(ty * 8 + r) * DD + k];
                acc[r][0] = fmaf(a, w.x, acc[r][0]);
                acc[r][1] = fmaf(a, w.y, acc[r][1]);
                acc[r][2] = fmaf(a, w.z, acc[r][2]);
                acc[r][3] = fmaf(a, w.w, acc[r][3]);
            }
        }

        float s0 = 0.f, s1 = 0.f, s2 = 0.f, s3 = 0.f;
        float q0 = 0.f, q1 = 0.f, q2 = 0.f, q3 = 0.f;
        #pragma unroll
        for (int r = 0; r < 8; r++) {
            int rr = ty * 8 + r;
            if (rr < rows) {
                float4 v = make_float4(acc[r][0], acc[r][1], acc[r][2], acc[r][3]);
                ((float4*)(g_h + (size_t)(row0 + rr) * DD))[tx] = v;
                s0 += v.x; q0 += v.x * v.x;
                s1 += v.y; q1 += v.y * v.y;
                s2 += v.z; q2 += v.z * v.z;
                s3 += v.w; q3 += v.w * v.w;
            }
        }
        int c = tx * 4;
        atomicAdd(&sS[c + 0], s0); atomicAdd(&sS[128 + c + 0], q0);
        atomicAdd(&sS[c + 1], s1); atomicAdd(&sS[128 + c + 1], q1);
        atomicAdd(&sS[c + 2], s2); atomicAdd(&sS[128 + c + 2], q2);
        atomicAdd(&sS[c + 3], s3); atomicAdd(&sS[128 + c + 3], q3);
        __syncthreads();
    }
    atomicAdd(&g_stats[layer * 256 + tid], (double)sS[tid]);
}

// ---------------- final: persistent; BN(from g_stats layer2)+relu; logits; softmax ----------------
#define FIN_TILES ((NN + 15) / 16)
__global__ void __launch_bounds__(128) k_final(
    const float* __restrict__ Wout, const float* __restrict__ log_tau,
    const float* __restrict__ gamma, const float* __restrict__ beta,
    float* __restrict__ out)
{
    __shared__ float sW[DD * KK];
    __shared__ float sZ[16 * DD];
    __shared__ float sSc[DD], sSh[DD];
    int tid = threadIdx.x;
    for (int i = tid; i < DD * KK / 4; i += 128)
        ((float4*)sW)[i] = ((const float4*)Wout)[i];
    {
        int c = tid;   // 128 threads == DD
        double s = g_stats[256 + c];
        double q = g_stats[256 + DD + c];
        float m = (float)(s / (double)NN);
        float v = (float)(q / (double)NN) - m * m;
        float sc = gamma[c] * rsqrtf(v + BN_EPS_F);
        sSc[c] = sc;
        sSh[c] = beta[c] - m * sc;
    }

    int warp = tid >> 5, lane = tid & 31;
    float inv_tau = expf(-*log_tau);

    for (int t = blockIdx.x; t < FIN_TILES; t += gridDim.x) {
        int row0 = t * 16;
        __syncthreads();
        for (int i = tid; i < 16 * DD / 4; i += 128) {
            int r = i >> 5;
            int c4 = i & 31;
            float4 v = make_float4(0.f, 0.f, 0.f, 0.f);
            int row = row0 + r;
            if (row < NN) {
                float4 hv = ((const float4*)(g_h + (size_t)row * DD))[c4];
                float4 sc = ((const float4*)sSc)[c4];
                float4 sh = ((const float4*)sSh)[c4];
                v.x = fmaxf(fmaf(hv.x, sc.x, sh.x), 0.f);
                v.y = fmaxf(fmaf(hv.y, sc.y, sh.y), 0.f);
                v.z = fmaxf(fmaf(hv.z, sc.z, sh.z), 0.f);
                v.w = fmaxf(fmaf(hv.w, sc.w, sh.w), 0.f);
            }
            ((float4*)sZ)[i] = v;
        }
        __syncthreads();

        float acc[4][2];
        #pragma unroll
        for (int r = 0; r < 4; r++) { acc[r][0] = 0.f; acc[r][1] = 0.f; }
        #pragma unroll 4
        for (int k = 0; k < DD; k++) {
            float w0 = sW[k * KK + lane];
            float w1 = sW[k * KK + 32 + lane];
            #pragma unroll
            for (int r = 0; r < 4; r++) {
                float z = sZ[(warp * 4 + r) * DD + k];
                acc[r][0] = fmaf(z, w0, acc[r][0]);
                acc[r][1] = fmaf(z, w1, acc[r][1]);
            }
        }

        #pragma unroll
        for (int r = 0; r < 4; r++) {
            int row = row0 + warp * 4 + r;
            if (row >= NN) continue;
            float l0 = acc[r][0], l1 = acc[r][1];
            out[(size_t)NN * KK + (size_t)row * KK + lane]      = l0;
            out[(size_t)NN * KK + (size_t)row * KK + 32 + lane] = l1;
            float a0 = l0 * inv_tau, a1 = l1 * inv_tau;
            float m = fmaxf(a0, a1);
            #pragma unroll
            for (int o = 16; o > 0; o >>= 1) m = fmaxf(m, __shfl_xor_sync(0xffffffffu, m, o));
            float e0 = expf(a0 - m), e1 = expf(a1 - m);
            float s = e0 + e1;
            #pragma unroll
            for (int o = 16; o > 0; o >>= 1) s += __shfl_xor_sync(0xffffffffu, s, o);
            float inv = 1.0f / s;
            out[(size_t)row * KK + lane]      = e0 * inv;
            out[(size_t)row * KK + 32 + lane] = e1 * inv;
        }
    }
}

// ---------------- launch ----------------
extern "C" void kernel_launch(void* const* d_in, const int* in_sizes, int n_in,
                              void* d_out, int out_size) {
    const float* x      = (const float*)d_in[0];
    const int*   ei     = (const int*)d_in[1];
    const float* W1a    = (const float*)d_in[2];
    const float* b1a    = (const float*)d_in[3];
    const float* W1b    = (const float*)d_in[4];
    const float* b1b    = (const float*)d_in[5];
    const float* eps1   = (const float*)d_in[6];
    const float* gamma1 = (const float*)d_in[7];
    const float* beta1  = (const float*)d_in[8];
    const float* W2a    = (const float*)d_in[9];
    const float* b2a    = (const float*)d_in[10];
    const float* W2b    = (const float*)d_in[11];
    const float* b2b    = (const float*)d_in[12];
    const float* eps2   = (const float*)d_in[13];
    const float* gamma2 = (const float*)d_in[14];
    const float* beta2  = (const float*)d_in[15];
    const float* Wout   = (const float*)d_in[16];
    const float* ltau   = (const float*)d_in[17];
    float* out = (float*)d_out;

    const int MLP_SMEM = 49408 * 4;   // 197632 B
    cudaFuncSetAttribute(k_mlp, cudaFuncAttributeMaxDynamicSharedMemorySize, MLP_SMEM);

    int n_blocks  = (NN + 255) / 256;
    int e_blocks  = (EE + 255) / 256;
    int gw_blocks = (NN * 32 + 255) / 256;

    // CSR build
    k_zero<<<n_blocks, 256>>>();
    k_hist<<<e_blocks, 256>>>(ei);
    k_scan1<<<SCAN_NB, 1024>>>();
    k_scan2<<<SCAN_NB, 1024>>>();
    k_permute<<<e_blocks, 256>>>(ei);

    // layer 1
    k_gather<<<gw_blocks, 256>>>(x, eps1);
    k_mlp<<<148, 256, MLP_SMEM>>>(W1a, b1a, W1b, b1b, 0);

    // layer 2 (BN computed in-kernel from g_stats; relu fused into gather)
    k_gather_bn<<<gw_blocks, 256>>>(eps2, gamma1, beta1);
    k_mlp<<<148, 256, MLP_SMEM>>>(W2a, b2a, W2b, b2b, 1);

    // final (BN layer-2 computed in-kernel)
    k_final<<<592, 128>>>(Wout, ltau, gamma2, beta2, out);
}

// round 14
// speedup vs baseline: 1.7689x; 1.0265x over previous
#include <cuda_runtime.h>
#include <cstdint>
#include <math.h>

#define NN 50000
#define EE 800000
#define DD 128
#define KK 64
#define BN_EPS_F 1e-5f
#define SCAN_NB 49

// ---------------- scratch (static device memory) ----------------
__device__ float  g_agg[NN * DD];
__device__ float  g_h[NN * DD];
__device__ double g_stats[4 * DD];
__device__ float  g_scale[DD];
__device__ float  g_shift[DD];
// CSR
__device__ int g_deg[NN], g_off[NN + 1], g_cursor[NN], g_csr[EE], g_bsum[SCAN_NB];
__device__ int g_scan_ctr;

// ---------------- zero degree + stats + scan counter ----------------
__global__ void k_zero() {
    int i = blockIdx.x * blockDim.x + threadIdx.x;
    if (i < NN) g_deg[i] = 0;
    if (i < 512) g_stats[i] = 0.0;
    if (i == 512) g_scan_ctr = 0;
}

// ---------------- in-degree histogram ----------------
__global__ void k_hist(const int* __restrict__ ei) {
    int e = blockIdx.x * blockDim.x + threadIdx.x;
    if (e >= EE) return;
    int d = __ldg(ei + EE + e);
    if ((unsigned)d < NN) atomicAdd(&g_deg[d], 1);
}

// ---------------- fused exclusive scan (single kernel, grid spin barrier) ----------------
// 49 blocks x 1024. Phase 1: local scan (excl kept in register), write bsum.
// Grid barrier via atomic counter (49 blocks all resident). Phase 2: add block prefix.
__global__ void __launch_bounds__(1024) k_scan() {
    __shared__ int swarp[32];
    __shared__ int partial[2];
    int b = blockIdx.x, tid = threadIdx.x;
    int lane = tid & 31, w = tid >> 5;
    int i = b * 1024 + tid;

    // --- phase 1: local exclusive scan ---
    int v = (i < NN) ? g_deg[i] : 0;
    int xv = v;
    #pragma unroll
    for (int o = 1; o < 32; o <<= 1) {
        int y = __shfl_up_sync(0xffffffffu, xv, o);
        if (lane >= o) xv += y;
    }
    if (lane == 31) swarp[w] = xv;
    __syncthreads();
    if (w == 0) {
        int y = swarp[lane];
        #pragma unroll
        for (int o = 1; o < 32; o <<= 1) {
            int z = __shfl_up_sync(0xffffffffu, y, o);
            if (lane >= o) y += z;
        }
        swarp[lane] = y;
    }
    __syncthreads();
    int excl = xv - v + (w > 0 ? swarp[w - 1] : 0);   // local exclusive prefix (register)
    if (tid == 1023) {
        g_bsum[b] = excl + v;
        __threadfence();
    }
    __syncthreads();

    // --- grid barrier ---
    if (tid == 0) {
        atomicAdd(&g_scan_ctr, 1);
        while (atomicAdd(&g_scan_ctr, 0) < SCAN_NB) { }
    }
    __syncthreads();
    __threadfence();

    // --- phase 2: block prefix over bsum ---
    int pv = 0;
    if (tid < 64) {
        if (tid < SCAN_NB && tid < b) pv = g_bsum[tid];
        #pragma unroll
        for (int o = 16; o > 0; o >>= 1) pv += __shfl_down_sync(0xffffffffu, pv, o);
        if ((tid & 31) == 0) partial[tid >> 5] = pv;
    }
    __syncthreads();
    int base = partial[0] + partial[1];
    if (i < NN) {
        int o = excl + base;
        g_off[i] = o;
        g_cursor[i] = o;
    }
    if (b == SCAN_NB - 1 && tid == 0) g_off[NN] = base + g_bsum[b];
}

// ---------------- permute ----------------
__global__ void k_permute(const int* __restrict__ ei) {
    int e = blockIdx.x * blockDim.x + threadIdx.x;
    if (e >= EE) return;
    int s = __ldg(ei + e);
    int d = __ldg(ei + EE + e);
    if ((unsigned)s >= NN || (unsigned)d >= NN) return;
    int pos = atomicAdd(&g_cursor[d], 1);
    g_csr[pos] = s;
}

// ---------------- gather (layer 1): agg[n] = (1+eps)*x[n] + sum x[j] ----------------
__global__ void k_gather(const float* __restrict__ feat, const float* __restrict__ epsp) {
    int gw = (blockIdx.x * blockDim.x + threadIdx.x) >> 5;
    int lane = threadIdx.x & 31;
    if (gw >= NN) return;
    float e = 1.0f + *epsp;
    float4 acc = __ldg((const float4*)(feat + (size_t)gw * DD) + lane);
    acc.x *= e; acc.y *= e; acc.z *= e; acc.w *= e;
    int beg = __ldg(&g_off[gw]);
    int end = __ldg(&g_off[gw + 1]);
    int j = beg;
    for (; j + 4 <= end; j += 4) {
        int s0 = __ldg(&g_csr[j]);
        int s1 = __ldg(&g_csr[j + 1]);
        int s2 = __ldg(&g_csr[j + 2]);
        int s3 = __ldg(&g_csr[j + 3]);
        float4 v0 = __ldg((const float4*)(feat + (size_t)s0 * DD) + lane);
        float4 v1 = __ldg((const float4*)(feat + (size_t)s1 * DD) + lane);
        float4 v2 = __ldg((const float4*)(feat + (size_t)s2 * DD) + lane);
        float4 v3 = __ldg((const float4*)(feat + (size_t)s3 * DD) + lane);
        acc.x += (v0.x + v1.x) + (v2.x + v3.x);
        acc.y += (v0.y + v1.y) + (v2.y + v3.y);
        acc.z += (v0.z + v1.z) + (v2.z + v3.z);
        acc.w += (v0.w + v1.w) + (v2.w + v3.w);
    }
    for (; j < end; j++) {
        int s = __ldg(&g_csr[j]);
        float4 v = __ldg((const float4*)(feat + (size_t)s * DD) + lane);
        acc.x += v.x; acc.y += v.y; acc.z += v.z; acc.w += v.w;
    }
    ((float4*)(g_agg + (size_t)gw * DD))[lane] = acc;
}

// ---------------- gather layer 2: fused BN+relu (scale/shift globals), reads g_h ----------------
__global__ void k_gather_bn(const float* __restrict__ epsp) {
    int gw = (blockIdx.x * blockDim.x + threadIdx.x) >> 5;
    int lane = threadIdx.x & 31;
    if (gw >= NN) return;
    float e = 1.0f + *epsp;
    float4 sc = ((const float4*)g_scale)[lane];
    float4 sh = ((const float4*)g_shift)[lane];

    #define BNZ(v) do { \
        (v).x = fmaxf(fmaf((v).x, sc.x, sh.x), 0.f); \
        (v).y = fmaxf(fmaf((v).y, sc.y, sh.y), 0.f); \
        (v).z = fmaxf(fmaf((v).z, sc.z, sh.z), 0.f); \
        (v).w = fmaxf(fmaf((v).w, sc.w, sh.w), 0.f); } while (0)

    float4 acc = __ldg((const float4*)(g_h + (size_t)gw * DD) + lane);
    BNZ(acc);
    acc.x *= e; acc.y *= e; acc.z *= e; acc.w *= e;
    int beg = __ldg(&g_off[gw]);
    int end = __ldg(&g_off[gw + 1]);
    int j = beg;
    for (; j + 4 <= end; j += 4) {
        int s0 = __ldg(&g_csr[j]);
        int s1 = __ldg(&g_csr[j + 1]);
        int s2 = __ldg(&g_csr[j + 2]);
        int s3 = __ldg(&g_csr[j + 3]);
        float4 v0 = __ldg((const float4*)(g_h + (size_t)s0 * DD) + lane);
        float4 v1 = __ldg((const float4*)(g_h + (size_t)s1 * DD) + lane);
        float4 v2 = __ldg((const float4*)(g_h + (size_t)s2 * DD) + lane);
        float4 v3 = __ldg((const float4*)(g_h + (size_t)s3 * DD) + lane);
        BNZ(v0); BNZ(v1); BNZ(v2); BNZ(v3);
        acc.x += (v0.x + v1.x) + (v2.x + v3.x);
        acc.y += (v0.y + v1.y) + (v2.y + v3.y);
        acc.z += (v0.z + v1.z) + (v2.z + v3.z);
        acc.w += (v0.w + v1.w) + (v2.w + v3.w);
    }
    for (; j < end; j++) {
        int s = __ldg(&g_csr[j]);
        float4 v = __ldg((const float4*)(g_h + (size_t)s * DD) + lane);
        BNZ(v);
        acc.x += v.x; acc.y += v.y; acc.z += v.z; acc.w += v.w;
    }
    #undef BNZ
    ((float4*)(g_agg + (size_t)gw * DD))[lane] = acc;
}

// ---------------- fused 2-GEMM MLP (fp32 FFMA) + BN stats ----------------
__global__ void __launch_bounds__(256, 1) k_mlp(
    const float* __restrict__ Wa, const float* __restrict__ ba,
    const float* __restrict__ Wb, const float* __restrict__ bb, int layer)
{
    extern __shared__ float sm[];
    float* sWa = sm;
    float* sWb = sm + 16384;
    float* sA  = sm + 32768;
    float* sT  = sm + 40960;
    float* sS  = sm + 49152;

    int tid = threadIdx.x;
    for (int i = tid; i < 4096; i += 256) {
        ((float4*)sWa)[i] = ((const float4*)Wa)[i];
        ((float4*)sWb)[i] = ((const float4*)Wb)[i];
    }
    sS[tid] = 0.0f;

    int tx = tid & 31;
    int ty = tid >> 5;
    float4 ba4 = *(const float4*)(ba + tx * 4);
    float4 bb4 = *(const float4*)(bb + tx * 4);
    __syncthreads();

    const int ntiles = (NN + 63) / 64;
    for (int t = blockIdx.x; t < ntiles; t += gridDim.x) {
        int row0 = t * 64;
        int rows = NN - row0; if (rows > 64) rows = 64;

        for (int i = tid; i < 2048; i += 256) {
            int r = i >> 5;
            float4 v = make_float4(0.f, 0.f, 0.f, 0.f);
            if (r < rows) v = ((const float4*)(g_agg + (size_t)(row0 + r) * DD))[i & 31];
            ((float4*)sA)[i] = v;
        }
        __syncthreads();

        float acc[8][4];
        #pragma unroll
        for (int r = 0; r < 8; r++) { acc[r][0] = ba4.x; acc[r][1] = ba4.y; acc[r][2] = ba4.z; acc[r][3] = ba4.w; }
        #pragma unroll 8
        for (int k = 0; k < DD; k++) {
            float4 w = ((const float4*)(sWa + k * DD))[tx];
            #pragma unroll
            for (int r = 0; r < 8; r++) {
                float a = sA[(ty * 8 + r) * DD + k];
                acc[r][0] = fmaf(a, w.x, acc[r][0]);
                acc[r][1] = fmaf(a, w.y, acc[r][1]);
                acc[r][2] = fmaf(a, w.z, acc[r][2]);
                acc[r][3] = fmaf(a, w.w, acc[r][3]);
            }
        }
        #pragma unroll
        for (int r = 0; r < 8; r++) {
            float4 v = make_float4(fmaxf(acc[r][0], 0.f), fmaxf(acc[r][1], 0.f),
                                   fmaxf(acc[r][2], 0.f), fmaxf(acc[r][3], 0.f));
            ((float4*)(sT + (ty * 8 + r) * DD))[tx] = v;
        }
        __syncthreads();

        #pragma unroll
        for (int r = 0; r < 8; r++) { acc[r][0] = bb4.x; acc[r][1] = bb4.y; acc[r][2] = bb4.z; acc[r][3] = bb4.w; }
        #pragma unroll 8
        for (int k = 0; k < DD; k++) {
            float4 w = ((const float4*)(sWb + k * DD))[tx];
            #pragma unroll
            for (int r = 0; r < 8; r++) {
                float a = sT[(ty * 8 + r) * DD + k];
                acc[r][0] = fmaf(a, w.x, acc[r][0]);
                acc[r][1] = fmaf(a, w.y, acc[r][1]);
                acc[r][2] = fmaf(a, w.z, acc[r][2]);
                acc[r][3] = fmaf(a, w.w, acc[r][3]);
            }
        }

        float s0 = 0.f, s1 = 0.f, s2 = 0.f, s3 = 0.f;
        float q0 = 0.f, q1 = 0.f, q2 = 0.f, q3 = 0.f;
        #pragma unroll
        for (int r = 0; r < 8; r++) {
            int rr = ty * 8 + r;
            if (rr < rows) {
                float4 v = make_float4(acc[r][0], acc[r][1], acc[r][2], acc[r][3]);
                ((float4*)(g_h + (size_t)(row0 + rr) * DD))[tx] = v;
                s0 += v.x; q0 += v.x * v.x;
                s1 += v.y; q1 += v.y * v.y;
                s2 += v.z; q2 += v.z * v.z;
                s3 += v.w; q3 += v.w * v.w;
            }
        }
        int c = tx * 4;
        atomicAdd(&sS[c + 0], s0); atomicAdd(&sS[128 + c + 0], q0);
        atomicAdd(&sS[c + 1], s1); atomicAdd(&sS[128 + c + 1], q1);
        atomicAdd(&sS[c + 2], s2); atomicAdd(&sS[128 + c + 2], q2);
        atomicAdd(&sS[c + 3], s3); atomicAdd(&sS[128 + c + 3], q3);
        __syncthreads();
    }
    atomicAdd(&g_stats[layer * 256 + tid], (double)sS[tid]);
}

// ---------------- BN finalize ----------------
__global__ void k_bnstats(const float* __restrict__ gamma, const float* __restrict__ beta, int layer) {
    int c = threadIdx.x;
    double s = g_stats[layer * 256 + c];
    double q = g_stats[layer * 256 + 128 + c];
    float m = (float)(s / (double)NN);
    float v = (float)(q / (double)NN) - m * m;
    float sc = gamma[c] * rsqrtf(v + BN_EPS_F);
    g_scale[c] = sc;
    g_shift[c] = beta[c] - m * sc;
}

// ---------------- final: persistent; z2 = relu(bn(h2)); logits; softmax ----------------
#define FIN_TILES ((NN + 15) / 16)
__global__ void __launch_bounds__(128) k_final(
    const float* __restrict__ Wout, const float* __restrict__ log_tau,
    float* __restrict__ out)
{
    __shared__ float sW[DD * KK];
    __shared__ float sZ[16 * DD];
    int tid = threadIdx.x;
    for (int i = tid; i < DD * KK / 4; i += 128)
        ((float4*)sW)[i] = ((const float4*)Wout)[i];

    int warp = tid >> 5, lane = tid & 31;
    float inv_tau = expf(-*log_tau);

    for (int t = blockIdx.x; t < FIN_TILES; t += gridDim.x) {
        int row0 = t * 16;
        __syncthreads();
        for (int i = tid; i < 16 * DD / 4; i += 128) {
            int r = i >> 5;
            int c4 = i & 31;
            float4 v = make_float4(0.f, 0.f, 0.f, 0.f);
            int row = row0 + r;
            if (row < NN) {
                float4 hv = ((const float4*)(g_h + (size_t)row * DD))[c4];
                float4 sc = ((const float4*)g_scale)[c4];
                float4 sh = ((const float4*)g_shift)[c4];
                v.x = fmaxf(fmaf(hv.x, sc.x, sh.x), 0.f);
                v.y = fmaxf(fmaf(hv.y, sc.y, sh.y), 0.f);
                v.z = fmaxf(fmaf(hv.z, sc.z, sh.z), 0.f);
                v.w = fmaxf(fmaf(hv.w, sc.w, sh.w), 0.f);
            }
            ((float4*)sZ)[i] = v;
        }
        __syncthreads();

        float acc[4][2];
        #pragma unroll
        for (int r = 0; r < 4; r++) { acc[r][0] = 0.f; acc[r][1] = 0.f; }
        #pragma unroll 4
        for (int k = 0; k < DD; k++) {
            float w0 = sW[k * KK + lane];
            float w1 = sW[k * KK + 32 + lane];
            #pragma unroll
            for (int r = 0; r < 4; r++) {
                float z = sZ[(warp * 4 + r) * DD + k];
                acc[r][0] = fmaf(z, w0, acc[r][0]);
                acc[r][1] = fmaf(z, w1, acc[r][1]);
            }
        }

        #pragma unroll
        for (int r = 0; r < 4; r++) {
            int row = row0 + warp * 4 + r;
            if (row >= NN) continue;
            float l0 = acc[r][0], l1 = acc[r][1];
            out[(size_t)NN * KK + (size_t)row * KK + lane]      = l0;
            out[(size_t)NN * KK + (size_t)row * KK + 32 + lane] = l1;
            float a0 = l0 * inv_tau, a1 = l1 * inv_tau;
            float m = fmaxf(a0, a1);
            #pragma unroll
            for (int o = 16; o > 0; o >>= 1) m = fmaxf(m, __shfl_xor_sync(0xffffffffu, m, o));
            float e0 = expf(a0 - m), e1 = expf(a1 - m);
            float s = e0 + e1;
            #pragma unroll
            for (int o = 16; o > 0; o >>= 1) s += __shfl_xor_sync(0xffffffffu, s, o);
            float inv = 1.0f / s;
            out[(size_t)row * KK + lane]      = e0 * inv;
            out[(size_t)row * KK + 32 + lane] = e1 * inv;
        }
    }
}

// ---------------- launch ----------------
extern "C" void kernel_launch(void* const* d_in, const int* in_sizes, int n_in,
                              void* d_out, int out_size) {
    const float* x      = (const float*)d_in[0];
    const int*   ei     = (const int*)d_in[1];
    const float* W1a    = (const float*)d_in[2];
    const float* b1a    = (const float*)d_in[3];
    const float* W1b    = (const float*)d_in[4];
    const float* b1b    = (const float*)d_in[5];
    const float* eps1   = (const float*)d_in[6];
    const float* gamma1 = (const float*)d_in[7];
    const float* beta1  = (const float*)d_in[8];
    const float* W2a    = (const float*)d_in[9];
    const float* b2a    = (const float*)d_in[10];
    const float* W2b    = (const float*)d_in[11];
    const float* b2b    = (const float*)d_in[12];
    const float* eps2   = (const float*)d_in[13];
    const float* gamma2 = (const float*)d_in[14];
    const float* beta2  = (const float*)d_in[15];
    const float* Wout   = (const float*)d_in[16];
    const float* ltau   = (const float*)d_in[17];
    float* out = (float*)d_out;

    const int MLP_SMEM = 49408 * 4;   // 197632 B
    cudaFuncSetAttribute(k_mlp, cudaFuncAttributeMaxDynamicSharedMemorySize, MLP_SMEM);

    int n_blocks  = (NN + 255) / 256;
    int e_blocks  = (EE + 255) / 256;
    int gw_blocks = (NN * 32 + 255) / 256;

    // CSR build (fused single-kernel scan)
    k_zero<<<n_blocks, 256>>>();
    k_hist<<<e_blocks, 256>>>(ei);
    k_scan<<<SCAN_NB, 1024>>>();
    k_permute<<<e_blocks, 256>>>(ei);

    // layer 1
    k_gather<<<gw_blocks, 256>>>(x, eps1);
    k_mlp<<<148, 256, MLP_SMEM>>>(W1a, b1a, W1b, b1b, 0);
    k_bnstats<<<1, 128>>>(gamma1, beta1, 0);

    // layer 2 (BN+relu fused into gather, scale/shift from globals)
    k_gather_bn<<<gw_blocks, 256>>>(eps2);
    k_mlp<<<148, 256, MLP_SMEM>>>(W2a, b2a, W2b, b2b, 1);
    k_bnstats<<<1, 128>>>(gamma2, beta2, 1);

    k_final<<<592, 128>>>(Wout, ltau, out);
}

// round 15
// speedup vs baseline: 1.7706x; 1.0010x over previous
#include <cuda_runtime.h>
#include <cstdint>
#include <math.h>

#define NN 50000
#define EE 800000
#define DD 128
#define KK 64
#define BN_EPS_F 1e-5f
#define SCAN_NB 49

// ---------------- scratch (static device memory) ----------------
__device__ float  g_agg[NN * DD];
__device__ float  g_h[NN * DD];
__device__ double g_stats[4 * DD];
__device__ float  g_scale[DD];
__device__ float  g_shift[DD];
// CSR
__device__ int g_deg[NN], g_off[NN + 1], g_cursor[NN], g_csr[EE], g_bsum[SCAN_NB];
__device__ int g_scan_ctr;
__device__ int g_mlp_ctr[2];

// ---------------- zero degree + stats + counters ----------------
__global__ void k_zero() {
    int i = blockIdx.x * blockDim.x + threadIdx.x;
    if (i < NN) g_deg[i] = 0;
    if (i < 512) g_stats[i] = 0.0;
    if (i == 512) g_scan_ctr = 0;
    if (i == 513) g_mlp_ctr[0] = 0;
    if (i == 514) g_mlp_ctr[1] = 0;
}

// ---------------- in-degree histogram ----------------
__global__ void k_hist(const int* __restrict__ ei) {
    int e = blockIdx.x * blockDim.x + threadIdx.x;
    if (e >= EE) return;
    int d = __ldg(ei + EE + e);
    if ((unsigned)d < NN) atomicAdd(&g_deg[d], 1);
}

// ---------------- fused exclusive scan (single kernel, grid spin barrier) ----------------
__global__ void __launch_bounds__(1024) k_scan() {
    __shared__ int swarp[32];
    __shared__ int partial[2];
    int b = blockIdx.x, tid = threadIdx.x;
    int lane = tid & 31, w = tid >> 5;
    int i = b * 1024 + tid;

    int v = (i < NN) ? g_deg[i] : 0;
    int xv = v;
    #pragma unroll
    for (int o = 1; o < 32; o <<= 1) {
        int y = __shfl_up_sync(0xffffffffu, xv, o);
        if (lane >= o) xv += y;
    }
    if (lane == 31) swarp[w] = xv;
    __syncthreads();
    if (w == 0) {
        int y = swarp[lane];
        #pragma unroll
        for (int o = 1; o < 32; o <<= 1) {
            int z = __shfl_up_sync(0xffffffffu, y, o);
            if (lane >= o) y += z;
        }
        swarp[lane] = y;
    }
    __syncthreads();
    int excl = xv - v + (w > 0 ? swarp[w - 1] : 0);
    if (tid == 1023) {
        g_bsum[b] = excl + v;
        __threadfence();
    }
    __syncthreads();

    if (tid == 0) {
        atomicAdd(&g_scan_ctr, 1);
        while (atomicAdd(&g_scan_ctr, 0) < SCAN_NB) { }
    }
    __syncthreads();
    __threadfence();

    int pv = 0;
    if (tid < 64) {
        if (tid < SCAN_NB && tid < b) pv = g_bsum[tid];
        #pragma unroll
        for (int o = 16; o > 0; o >>= 1) pv += __shfl_down_sync(0xffffffffu, pv, o);
        if ((tid & 31) == 0) partial[tid >> 5] = pv;
    }
    __syncthreads();
    int base = partial[0] + partial[1];
    if (i < NN) {
        int o = excl + base;
        g_off[i] = o;
        g_cursor[i] = o;
    }
    if (b == SCAN_NB - 1 && tid == 0) g_off[NN] = base + g_bsum[b];
}

// ---------------- permute ----------------
__global__ void k_permute(const int* __restrict__ ei) {
    int e = blockIdx.x * blockDim.x + threadIdx.x;
    if (e >= EE) return;
    int s = __ldg(ei + e);
    int d = __ldg(ei + EE + e);
    if ((unsigned)s >= NN || (unsigned)d >= NN) return;
    int pos = atomicAdd(&g_cursor[d], 1);
    g_csr[pos] = s;
}

// ---------------- gather (layer 1): agg[n] = (1+eps)*x[n] + sum x[j] ----------------
__global__ void k_gather(const float* __restrict__ feat, const float* __restrict__ epsp) {
    int gw = (blockIdx.x * blockDim.x + threadIdx.x) >> 5;
    int lane = threadIdx.x & 31;
    if (gw >= NN) return;
    float e = 1.0f + *epsp;
    float4 acc = __ldg((const float4*)(feat + (size_t)gw * DD) + lane);
    acc.x *= e; acc.y *= e; acc.z *= e; acc.w *= e;
    int beg = __ldg(&g_off[gw]);
    int end = __ldg(&g_off[gw + 1]);
    int j = beg;
    for (; j + 4 <= end; j += 4) {
        int s0 = __ldg(&g_csr[j]);
        int s1 = __ldg(&g_csr[j + 1]);
        int s2 = __ldg(&g_csr[j + 2]);
        int s3 = __ldg(&g_csr[j + 3]);
        float4 v0 = __ldg((const float4*)(feat + (size_t)s0 * DD) + lane);
        float4 v1 = __ldg((const float4*)(feat + (size_t)s1 * DD) + lane);
        float4 v2 = __ldg((const float4*)(feat + (size_t)s2 * DD) + lane);
        float4 v3 = __ldg((const float4*)(feat + (size_t)s3 * DD) + lane);
        acc.x += (v0.x + v1.x) + (v2.x + v3.x);
        acc.y += (v0.y + v1.y) + (v2.y + v3.y);
        acc.z += (v0.z + v1.z) + (v2.z + v3.z);
        acc.w += (v0.w + v1.w) + (v2.w + v3.w);
    }
    for (; j < end; j++) {
        int s = __ldg(&g_csr[j]);
        float4 v = __ldg((const float4*)(feat + (size_t)s * DD) + lane);
        acc.x += v.x; acc.y += v.y; acc.z += v.z; acc.w += v.w;
    }
    ((float4*)(g_agg + (size_t)gw * DD))[lane] = acc;
}

// ---------------- gather layer 2: fused BN+relu (scale/shift globals), reads g_h ----------------
__global__ void k_gather_bn(const float* __restrict__ epsp) {
    int gw = (blockIdx.x * blockDim.x + threadIdx.x) >> 5;
    int lane = threadIdx.x & 31;
    if (gw >= NN) return;
    float e = 1.0f + *epsp;
    float4 sc = ((const float4*)g_scale)[lane];
    float4 sh = ((const float4*)g_shift)[lane];

    #define BNZ(v) do { \
        (v).x = fmaxf(fmaf((v).x, sc.x, sh.x), 0.f); \
        (v).y = fmaxf(fmaf((v).y, sc.y, sh.y), 0.f); \
        (v).z = fmaxf(fmaf((v).z, sc.z, sh.z), 0.f); \
        (v).w = fmaxf(fmaf((v).w, sc.w, sh.w), 0.f); } while (0)

    float4 acc = __ldg((const float4*)(g_h + (size_t)gw * DD) + lane);
    BNZ(acc);
    acc.x *= e; acc.y *= e; acc.z *= e; acc.w *= e;
    int beg = __ldg(&g_off[gw]);
    int end = __ldg(&g_off[gw + 1]);
    int j = beg;
    for (; j + 4 <= end; j += 4) {
        int s0 = __ldg(&g_csr[j]);
        int s1 = __ldg(&g_csr[j + 1]);
        int s2 = __ldg(&g_csr[j + 2]);
        int s3 = __ldg(&g_csr[j + 3]);
        float4 v0 = __ldg((const float4*)(g_h + (size_t)s0 * DD) + lane);
        float4 v1 = __ldg((const float4*)(g_h + (size_t)s1 * DD) + lane);
        float4 v2 = __ldg((const float4*)(g_h + (size_t)s2 * DD) + lane);
        float4 v3 = __ldg((const float4*)(g_h + (size_t)s3 * DD) + lane);
        BNZ(v0); BNZ(v1); BNZ(v2); BNZ(v3);
        acc.x += (v0.x + v1.x) + (v2.x + v3.x);
        acc.y += (v0.y + v1.y) + (v2.y + v3.y);
        acc.z += (v0.z + v1.z) + (v2.z + v3.z);
        acc.w += (v0.w + v1.w) + (v2.w + v3.w);
    }
    for (; j < end; j++) {
        int s = __ldg(&g_csr[j]);
        float4 v = __ldg((const float4*)(g_h + (size_t)s * DD) + lane);
        BNZ(v);
        acc.x += v.x; acc.y += v.y; acc.z += v.z; acc.w += v.w;
    }
    #undef BNZ
    ((float4*)(g_agg + (size_t)gw * DD))[lane] = acc;
}

// ---------------- fused 2-GEMM MLP (fp32 FFMA) + BN stats + last-block BN finalize ----------------
__global__ void __launch_bounds__(256, 1) k_mlp(
    const float* __restrict__ Wa, const float* __restrict__ ba,
    const float* __restrict__ Wb, const float* __restrict__ bb,
    const float* __restrict__ gamma, const float* __restrict__ beta, int layer)
{
    extern __shared__ float sm[];
    float* sWa = sm;
    float* sWb = sm + 16384;
    float* sA  = sm + 32768;
    float* sT  = sm + 40960;
    float* sS  = sm + 49152;
    __shared__ int sLast;

    int tid = threadIdx.x;
    for (int i = tid; i < 4096; i += 256) {
        ((float4*)sWa)[i] = ((const float4*)Wa)[i];
        ((float4*)sWb)[i] = ((const float4*)Wb)[i];
    }
    sS[tid] = 0.0f;

    int tx = tid & 31;
    int ty = tid >> 5;
    float4 ba4 = *(const float4*)(ba + tx * 4);
    float4 bb4 = *(const float4*)(bb + tx * 4);
    __syncthreads();

    const int ntiles = (NN + 63) / 64;
    for (int t = blockIdx.x; t < ntiles; t += gridDim.x) {
        int row0 = t * 64;
        int rows = NN - row0; if (rows > 64) rows = 64;

        for (int i = tid; i < 2048; i += 256) {
            int r = i >> 5;
            float4 v = make_float4(0.f, 0.f, 0.f, 0.f);
            if (r < rows) v = ((const float4*)(g_agg + (size_t)(row0 + r) * DD))[i & 31];
            ((float4*)sA)[i] = v;
        }
        __syncthreads();

        float acc[8][4];
        #pragma unroll
        for (int r = 0; r < 8; r++) { acc[r][0] = ba4.x; acc[r][1] = ba4.y; acc[r][2] = ba4.z; acc[r][3] = ba4.w; }
        #pragma unroll 8
        for (int k = 0; k < DD; k++) {
            float4 w = ((const float4*)(sWa + k * DD))[tx];
            #pragma unroll
            for (int r = 0; r < 8; r++) {
                float a = sA[(ty * 8 + r) * DD + k];
                acc[r][0] = fmaf(a, w.x, acc[r][0]);
                acc[r][1] = fmaf(a, w.y, acc[r][1]);
                acc[r][2] = fmaf(a, w.z, acc[r][2]);
                acc[r][3] = fmaf(a, w.w, acc[r][3]);
            }
        }
        #pragma unroll
        for (int r = 0; r < 8; r++) {
            float4 v = make_float4(fmaxf(acc[r][0], 0.f), fmaxf(acc[r][1], 0.f),
                                   fmaxf(acc[r][2], 0.f), fmaxf(acc[r][3], 0.f));
            ((float4*)(sT + (ty * 8 + r) * DD))[tx] = v;
        }
        __syncthreads();

        #pragma unroll
        for (int r = 0; r < 8; r++) { acc[r][0] = bb4.x; acc[r][1] = bb4.y; acc[r][2] = bb4.z; acc[r][3] = bb4.w; }
        #pragma unroll 8
        for (int k = 0; k < DD; k++) {
            float4 w = ((const float4*)(sWb + k * DD))[tx];
            #pragma unroll
            for (int r = 0; r < 8; r++) {
                float a = sT[(ty * 8 + r) * DD + k];
                acc[r][0] = fmaf(a, w.x, acc[r][0]);
                acc[r][1] = fmaf(a, w.y, acc[r][1]);
                acc[r][2] = fmaf(a, w.z, acc[r][2]);
                acc[r][3] = fmaf(a, w.w, acc[r][3]);
            }
        }

        float s0 = 0.f, s1 = 0.f, s2 = 0.f, s3 = 0.f;
        float q0 = 0.f, q1 = 0.f, q2 = 0.f, q3 = 0.f;
        #pragma unroll
        for (int r = 0; r < 8; r++) {
            int rr = ty * 8 + r;
            if (rr < rows) {
                float4 v = make_float4(acc[r][0], acc[r][1], acc[r][2], acc[r][3]);
                ((float4*)(g_h + (size_t)(row0 + rr) * DD))[tx] = v;
                s0 += v.x; q0 += v.x * v.x;
                s1 += v.y; q1 += v.y * v.y;
                s2 += v.z; q2 += v.z * v.z;
                s3 += v.w; q3 += v.w * v.w;
            }
        }
        int c = tx * 4;
        atomicAdd(&sS[c + 0], s0); atomicAdd(&sS[128 + c + 0], q0);
        atomicAdd(&sS[c + 1], s1); atomicAdd(&sS[128 + c + 1], q1);
        atomicAdd(&sS[c + 2], s2); atomicAdd(&sS[128 + c + 2], q2);
        atomicAdd(&sS[c + 3], s3); atomicAdd(&sS[128 + c + 3], q3);
        __syncthreads();
    }
    // flush block stats
    atomicAdd(&g_stats[layer * 256 + tid], (double)sS[tid]);

    // last-block BN finalize
    if (tid == 0) {
        __threadfence();
        int old = atomicAdd(&g_mlp_ctr[layer], 1);
        sLast = (old == gridDim.x - 1);
    }
    __syncthreads();
    if (sLast) {
        __threadfence();
        if (tid < DD) {
            int c = tid;
            double s = g_stats[layer * 256 + c];
            double q = g_stats[layer * 256 + 128 + c];
            float m = (float)(s / (double)NN);
            float v = (float)(q / (double)NN) - m * m;
            float sc = gamma[c] * rsqrtf(v + BN_EPS_F);
            g_scale[c] = sc;
            g_shift[c] = beta[c] - m * sc;
        }
    }
}

// ---------------- final: persistent; z2 = relu(bn(h2)); logits; softmax ----------------
#define FIN_TILES ((NN + 15) / 16)
__global__ void __launch_bounds__(128) k_final(
    const float* __restrict__ Wout, const float* __restrict__ log_tau,
    float* __restrict__ out)
{
    __shared__ float sW[DD * KK];
    __shared__ float sZ[16 * DD];
    int tid = threadIdx.x;
    for (int i = tid; i < DD * KK / 4; i += 128)
        ((float4*)sW)[i] = ((const float4*)Wout)[i];

    int warp = tid >> 5, lane = tid & 31;
    float inv_tau = expf(-*log_tau);

    for (int t = blockIdx.x; t < FIN_TILES; t += gridDim.x) {
        int row0 = t * 16;
        __syncthreads();
        for (int i = tid; i < 16 * DD / 4; i += 128) {
            int r = i >> 5;
            int c4 = i & 31;
            float4 v = make_float4(0.f, 0.f, 0.f, 0.f);
            int row = row0 + r;
            if (row < NN) {
                float4 hv = ((const float4*)(g_h + (size_t)row * DD))[c4];
                float4 sc = ((const float4*)g_scale)[c4];
                float4 sh = ((const float4*)g_shift)[c4];
                v.x = fmaxf(fmaf(hv.x, sc.x, sh.x), 0.f);
                v.y = fmaxf(fmaf(hv.y, sc.y, sh.y), 0.f);
                v.z = fmaxf(fmaf(hv.z, sc.z, sh.z), 0.f);
                v.w = fmaxf(fmaf(hv.w, sc.w, sh.w), 0.f);
            }
            ((float4*)sZ)[i] = v;
        }
        __syncthreads();

        float acc[4][2];
        #pragma unroll
        for (int r = 0; r < 4; r++) { acc[r][0] = 0.f; acc[r][1] = 0.f; }
        #pragma unroll 4
        for (int k = 0; k < DD; k++) {
            float w0 = sW[k * KK + lane];
            float w1 = sW[k * KK + 32 + lane];
            #pragma unroll
            for (int r = 0; r < 4; r++) {
                float z = sZ[(warp * 4 + r) * DD + k];
                acc[r][0] = fmaf(z, w0, acc[r][0]);
                acc[r][1] = fmaf(z, w1, acc[r][1]);
            }
        }

        #pragma unroll
        for (int r = 0; r < 4; r++) {
            int row = row0 + warp * 4 + r;
            if (row >= NN) continue;
            float l0 = acc[r][0], l1 = acc[r][1];
            out[(size_t)NN * KK + (size_t)row * KK + lane]      = l0;
            out[(size_t)NN * KK + (size_t)row * KK + 32 + lane] = l1;
            float a0 = l0 * inv_tau, a1 = l1 * inv_tau;
            float m = fmaxf(a0, a1);
            #pragma unroll
            for (int o = 16; o > 0; o >>= 1) m = fmaxf(m, __shfl_xor_sync(0xffffffffu, m, o));
            float e0 = expf(a0 - m), e1 = expf(a1 - m);
            float s = e0 + e1;
            #pragma unroll
            for (int o = 16; o > 0; o >>= 1) s += __shfl_xor_sync(0xffffffffu, s, o);
            float inv = 1.0f / s;
            out[(size_t)row * KK + lane]      = e0 * inv;
            out[(size_t)row * KK + 32 + lane] = e1 * inv;
        }
    }
}

// ---------------- launch ----------------
extern "C" void kernel_launch(void* const* d_in, const int* in_sizes, int n_in,
                              void* d_out, int out_size) {
    const float* x      = (const float*)d_in[0];
    const int*   ei     = (const int*)d_in[1];
    const float* W1a    = (const float*)d_in[2];
    const float* b1a    = (const float*)d_in[3];
    const float* W1b    = (const float*)d_in[4];
    const float* b1b    = (const float*)d_in[5];
    const float* eps1   = (const float*)d_in[6];
    const float* gamma1 = (const float*)d_in[7];
    const float* beta1  = (const float*)d_in[8];
    const float* W2a    = (const float*)d_in[9];
    const float* b2a    = (const float*)d_in[10];
    const float* W2b    = (const float*)d_in[11];
    const float* b2b    = (const float*)d_in[12];
    const float* eps2   = (const float*)d_in[13];
    const float* gamma2 = (const float*)d_in[14];
    const float* beta2  = (const float*)d_in[15];
    const float* Wout   = (const float*)d_in[16];
    const float* ltau   = (const float*)d_in[17];
    float* out = (float*)d_out;

    const int MLP_SMEM = 49408 * 4;   // 197632 B
    cudaFuncSetAttribute(k_mlp, cudaFuncAttributeMaxDynamicSharedMemorySize, MLP_SMEM);

    int n_blocks  = (NN + 255) / 256;
    int e_blocks  = (EE + 255) / 256;
    int gw_blocks = (NN * 32 + 255) / 256;

    // CSR build (fused single-kernel scan)
    k_zero<<<n_blocks, 256>>>();
    k_hist<<<e_blocks, 256>>>(ei);
    k_scan<<<SCAN_NB, 1024>>>();
    k_permute<<<e_blocks, 256>>>(ei);

    // layer 1 (BN finalize fused into last MLP block)
    k_gather<<<gw_blocks, 256>>>(x, eps1);
    k_mlp<<<148, 256, MLP_SMEM>>>(W1a, b1a, W1b, b1b, gamma1, beta1, 0);

    // layer 2
    k_gather_bn<<<gw_blocks, 256>>>(eps2);
    k_mlp<<<148, 256, MLP_SMEM>>>(W2a, b2a, W2b, b2b, gamma2, beta2, 1);

    k_final<<<592, 128>>>(Wout, ltau, out);
}